// round 7
// baseline (speedup 1.0000x reference)
#include <cuda_runtime.h>
#include <cuda_bf16.h>
#include <cstdint>

#define NRES  384
#define NSEQ  256
#define NFEAT 64
#define NPROJ 32
#define NOUT  128
#define ICDIM (NRES*NPROJ)          // 12288
#define NPAIR (NRES*NRES)           // 147456
#define CD    (NPROJ*NPROJ)         // 1024
#define LN_EPS 1e-5f

// ------------------------- scratch (device globals) -------------------------
__device__ __nv_bfloat16 g_Lt[(size_t)ICDIM*NSEQ];   // [m=(i,c)][s]  K-major
__device__ __nv_bfloat16 g_Rt[(size_t)ICDIM*NSEQ];   // [n=(j,d)][s]  K-major
__device__ __nv_bfloat16 g_O [(size_t)NPAIR*CD];     // [(i,j)][(c,d)]
__device__ __nv_bfloat16 g_Wob[NOUT*CD];             // Wo bf16 [o][cd]
__device__ float         g_normv[NPAIR];

// ------------------------- helpers -------------------------
__device__ __forceinline__ uint32_t smem_u32(const void* p){
    uint32_t a;
    asm("{ .reg .u64 t; cvta.to.shared.u64 t, %1; cvt.u32.u64 %0, t; }":"=r"(a):"l"(p));
    return a;
}
__device__ __forceinline__ void ldsm4(uint32_t& r0, uint32_t& r1, uint32_t& r2, uint32_t& r3, uint32_t a){
    asm volatile("ldmatrix.sync.aligned.m8n8.x4.shared.b16 {%0,%1,%2,%3}, [%4];"
        : "=r"(r0),"=r"(r1),"=r"(r2),"=r"(r3) : "r"(a));
}
__device__ __forceinline__ void mma16816(float* c, const uint32_t* a, uint32_t b0, uint32_t b1){
    asm volatile("mma.sync.aligned.m16n8k16.row.col.f32.bf16.bf16.f32 "
        "{%0,%1,%2,%3}, {%4,%5,%6,%7}, {%8,%9}, {%0,%1,%2,%3};"
        : "+f"(c[0]),"+f"(c[1]),"+f"(c[2]),"+f"(c[3])
        : "r"(a[0]),"r"(a[1]),"r"(a[2]),"r"(a[3]),"r"(b0),"r"(b1));
}
__device__ __forceinline__ uint32_t packbf2(float a, float b){
    __nv_bfloat162 h = __floats2bfloat162_rn(a, b);
    return *(uint32_t*)&h;
}
#define CP16(dst, src) asm volatile("cp.async.cg.shared.global [%0], [%1], 16;" \
    :: "r"(dst), "l"(src) : "memory")
#define CP_COMMIT() asm volatile("cp.async.commit_group;" ::: "memory")
#define CP_WAIT(n)  asm volatile("cp.async.wait_group %0;" :: "n"(n) : "memory")

// ---------------------------------------------------------------------------
// prep: LN + projections + mask; write transposed bf16 g_Lt/g_Rt.
// grid=384 (block per residue i), 256 threads (thread per s).
// ---------------------------------------------------------------------------
#define PREP_SMEM (4096*4 + 2*8192*2)   // 49152
__global__ void __launch_bounds__(256,2)
prep_kernel(const float* __restrict__ M, const float* __restrict__ mask,
            const float* __restrict__ gamma, const float* __restrict__ beta,
            const float* __restrict__ Wa, const float* __restrict__ ba,
            const float* __restrict__ Wb, const float* __restrict__ bb)
{
    extern __shared__ float ps[];
    float* sWa = ps;
    float* sWb = ps + 2048;
    __nv_bfloat16* sLb = (__nv_bfloat16*)(ps + 4096);  // [32][256]
    __nv_bfloat16* sRb = sLb + 8192;

    const int i = blockIdx.x;
    const int tid = threadIdx.x;
    for (int u = tid; u < NPROJ*NFEAT; u += 256){ sWa[u] = Wa[u]; sWb[u] = Wb[u]; }

    const int s = tid;
    const float4* mr = (const float4*)(M + ((size_t)s*NRES + i)*NFEAT);
    float4 mn[16];
    float s1 = 0.f, s2 = 0.f;
    #pragma unroll
    for (int q = 0; q < 16; q++){
        float4 v = mr[q]; mn[q] = v;
        s1 += v.x + v.y + v.z + v.w;
        s2 += v.x*v.x + v.y*v.y + v.z*v.z + v.w*v.w;
    }
    float mu  = s1 * (1.f/64.f);
    float var = s2 * (1.f/64.f) - mu*mu;
    float inv = rsqrtf(var + LN_EPS);
    const float4* g4 = (const float4*)gamma;
    const float4* b4 = (const float4*)beta;
    #pragma unroll
    for (int q = 0; q < 16; q++){
        float4 gg = g4[q], be = b4[q];
        mn[q].x = (mn[q].x - mu)*inv*gg.x + be.x;
        mn[q].y = (mn[q].y - mu)*inv*gg.y + be.y;
        mn[q].z = (mn[q].z - mu)*inv*gg.z + be.z;
        mn[q].w = (mn[q].w - mu)*inv*gg.w + be.w;
    }
    const float msk = mask[(size_t)s*NRES + i];
    __syncthreads();

    #pragma unroll 4
    for (int c = 0; c < NPROJ; c++){
        float accA = ba[c], accB = bb[c];
        const float4* wa = (const float4*)(sWa + c*NFEAT);
        const float4* wb = (const float4*)(sWb + c*NFEAT);
        #pragma unroll
        for (int q = 0; q < 16; q++){
            float4 w1 = wa[q], w2 = wb[q], v = mn[q];
            accA += v.x*w1.x + v.y*w1.y + v.z*w1.z + v.w*w1.w;
            accB += v.x*w2.x + v.y*w2.y + v.z*w2.z + v.w*w2.w;
        }
        sLb[c*256 + s] = __float2bfloat16(msk*accA);
        sRb[c*256 + s] = __float2bfloat16(msk*accB);
    }
    __syncthreads();

    for (int u = tid; u < NPROJ*128; u += 256){
        int c = u >> 7, sp = (u & 127) << 1;
        *(uint32_t*)(g_Lt + ((size_t)(i*NPROJ + c))*NSEQ + sp) = *(const uint32_t*)(sLb + c*256 + sp);
        *(uint32_t*)(g_Rt + ((size_t)(i*NPROJ + c))*NSEQ + sp) = *(const uint32_t*)(sRb + c*256 + sp);
    }
}

// ---------------------------------------------------------------------------
__global__ void norm_kernel(const float* __restrict__ mask)
{
    const int i = blockIdx.x, j = threadIdx.x;
    float acc = 0.0f;
    for (int s = 0; s < NSEQ; s++)
        acc += mask[s*NRES + i] * mask[s*NRES + j];
    g_normv[i*NRES + j] = acc;
}

__global__ void wconv_kernel(const float* __restrict__ Wo)
{
    int idx = blockIdx.x*256 + threadIdx.x;
    g_Wob[idx] = __float2bfloat16(Wo[idx]);
}

// ---------------------------------------------------------------------------
// gemm1: O[128x128] = Lt[it*128..] @ Rt[jt*128..]^T, K=256.
// 128 threads, 4 warps, 64x64 warp tiles. 3-stage cp.async ring (96KB), occ 2.
// Smem-staged coalesced epilogue.
// ---------------------------------------------------------------------------
#define G1_SMEM (3*32768)
#define OSTR 136                     // bf16 stride of epilogue tile (68 words)
__global__ void __launch_bounds__(128,2) gemm1_kernel()
{
    extern __shared__ char sm1[];
    const int tid = threadIdx.x, lane = tid & 31, w = tid >> 5;
    const int it = blockIdx.y, jt = blockIdx.x;
    const int wr = w >> 1, wc = w & 1;
    const int m0 = wr*64, n0 = wc*64;
    const int lo7 = lane & 7, hi = lane >> 4, l15 = lane & 15;

    const uint32_t sb = smem_u32(sm1);
    const int lrb = tid >> 3;        // 0..15
    const int lc  = tid & 7;         // 16B-unit col 0..7

    #define G1_LOAD(kc, s) do {                                               \
        _Pragma("unroll")                                                     \
        for (int q = 0; q < 8; q++){                                          \
            int row = q*16 + lrb;                                             \
            int cp = lc ^ (row & 7);                                          \
            uint32_t da = sb + (s)*32768 + row*128 + cp*16;                   \
            CP16(da,         (const void*)(g_Lt + ((size_t)(it*128 + row))*NSEQ + (kc)*64 + lc*8)); \
            CP16(da + 16384, (const void*)(g_Rt + ((size_t)(jt*128 + row))*NSEQ + (kc)*64 + lc*8)); \
        }                                                                     \
    } while(0)

    float acc[4][8][4];
    #pragma unroll
    for (int a = 0; a < 4; a++)
        #pragma unroll
        for (int b = 0; b < 8; b++)
            #pragma unroll
            for (int c = 0; c < 4; c++) acc[a][b][c] = 0.f;

    G1_LOAD(0, 0); CP_COMMIT();
    G1_LOAD(1, 1); CP_COMMIT();

    #pragma unroll 1
    for (int kc = 0; kc < 4; kc++){
        if (kc + 2 < 4){ G1_LOAD(kc+2, (kc+2)%3); CP_COMMIT(); CP_WAIT(2); }
        else if (kc + 1 < 4){ CP_WAIT(1); }
        else { CP_WAIT(0); }
        __syncthreads();
        const uint32_t sA = sb + (kc%3)*32768;
        const uint32_t sB = sA + 16384;
        #pragma unroll
        for (int ks = 0; ks < 4; ks++){
            int ch = ((ks*2 + hi) ^ lo7) << 4;
            uint32_t a[4][4], b[4][4];
            #pragma unroll
            for (int mt = 0; mt < 4; mt++)
                ldsm4(a[mt][0],a[mt][1],a[mt][2],a[mt][3],
                      sA + (m0 + mt*16 + l15)*128 + ch);
            #pragma unroll
            for (int nb = 0; nb < 4; nb++)
                ldsm4(b[nb][0],b[nb][1],b[nb][2],b[nb][3],
                      sB + (n0 + nb*16 + l15)*128 + ch);
            #pragma unroll
            for (int mt = 0; mt < 4; mt++){
                #pragma unroll
                for (int nb = 0; nb < 4; nb++){
                    mma16816(acc[mt][nb*2],   a[mt], b[nb][0], b[nb][2]);
                    mma16816(acc[mt][nb*2+1], a[mt], b[nb][1], b[nb][3]);
                }
            }
        }
        __syncthreads();
    }

    // -------- epilogue: stage bf16 tile in smem, then coalesced stores -----
    __nv_bfloat16* Ot = (__nv_bfloat16*)sm1;     // [128][OSTR]
    const int rbase = lane >> 2, cpair = (lane & 3)*2;
    #pragma unroll
    for (int mt = 0; mt < 4; mt++){
        int r0 = m0 + mt*16 + rbase;
        int r1 = r0 + 8;
        #pragma unroll
        for (int nt = 0; nt < 8; nt++){
            int col = n0 + nt*8 + cpair;
            *(uint32_t*)(Ot + r0*OSTR + col) = packbf2(acc[mt][nt][0], acc[mt][nt][1]);
            *(uint32_t*)(Ot + r1*OSTR + col) = packbf2(acc[mt][nt][2], acc[mt][nt][3]);
        }
    }
    __syncthreads();
    // 16 pairs, each 1024 bf16 contiguous in g_O
    #pragma unroll 1
    for (int p = 0; p < 16; p++){
        int ri = p >> 2, cj = p & 3;
        size_t gbase = (((size_t)(it*4 + ri)*NRES + jt*4 + cj) << 10);
        int c  = tid >> 2;            // 0..31
        int d8 = (tid & 3) * 8;       // 0,8,16,24
        uint4 v = *(const uint4*)(Ot + (ri*32 + c)*OSTR + cj*32 + d8);
        *(uint4*)(g_O + gbase + c*32 + d8) = v;
    }
}

// ---------------------------------------------------------------------------
// gemm2: Z[m,o] = sum_k O[m,k]*Wob[o,k], m-tile 128, o=128, K=1024.
// 128 threads, 4 warps, 64x64 warp tiles, 3-stage cp.async.
// Smem-staged fused epilogue (coalesced float4).
// ---------------------------------------------------------------------------
#define G2_SMEM (3*32768)
#define ZSTR 132                     // fp32 stride of epilogue tile
__global__ void __launch_bounds__(128,2)
gemm2_kernel(const float* __restrict__ Zraw, const float* __restrict__ bo,
             float* __restrict__ out)
{
    extern __shared__ char sm2[];
    __shared__ float sbo[NOUT];
    const int tid = threadIdx.x, lane = tid & 31, w = tid >> 5;
    const int m0 = blockIdx.x * 128;
    const int wr = w >> 1, wc = w & 1;
    const int mw0 = wr*64, o0 = wc*64;
    const int lo7 = lane & 7, hi = lane >> 4, l15 = lane & 15;

    const uint32_t sb = smem_u32(sm2);
    if (tid < NOUT) sbo[tid] = bo[tid];

    const int lrb = tid >> 3;
    const int lc  = tid & 7;

    #define G2_LOAD(kc, s) do {                                               \
        _Pragma("unroll")                                                     \
        for (int q = 0; q < 8; q++){                                          \
            int row = q*16 + lrb;                                             \
            int cp = lc ^ (row & 7);                                          \
            uint32_t da = sb + (s)*32768 + row*128 + cp*16;                   \
            CP16(da,         (const void*)(g_O   + (size_t)(m0 + row)*CD + (kc)*64 + lc*8)); \
            CP16(da + 16384, (const void*)(g_Wob + (size_t)row*CD        + (kc)*64 + lc*8)); \
        }                                                                     \
    } while(0)

    float acc[4][8][4];
    #pragma unroll
    for (int a = 0; a < 4; a++)
        #pragma unroll
        for (int b = 0; b < 8; b++)
            #pragma unroll
            for (int c = 0; c < 4; c++) acc[a][b][c] = 0.f;

    G2_LOAD(0, 0); CP_COMMIT();
    G2_LOAD(1, 1); CP_COMMIT();

    #pragma unroll 1
    for (int kc = 0; kc < 16; kc++){
        if (kc + 2 < 16){ G2_LOAD(kc+2, (kc+2)%3); CP_COMMIT(); CP_WAIT(2); }
        else if (kc + 1 < 16){ CP_WAIT(1); }
        else { CP_WAIT(0); }
        __syncthreads();
        const uint32_t sA = sb + (kc%3)*32768;
        const uint32_t sB = sA + 16384;
        #pragma unroll
        for (int ks = 0; ks < 4; ks++){
            int ch = ((ks*2 + hi) ^ lo7) << 4;
            uint32_t a[4][4], b[4][4];
            #pragma unroll
            for (int mt = 0; mt < 4; mt++)
                ldsm4(a[mt][0],a[mt][1],a[mt][2],a[mt][3],
                      sA + (mw0 + mt*16 + l15)*128 + ch);
            #pragma unroll
            for (int nb = 0; nb < 4; nb++)
                ldsm4(b[nb][0],b[nb][1],b[nb][2],b[nb][3],
                      sB + (o0 + nb*16 + l15)*128 + ch);
            #pragma unroll
            for (int mt = 0; mt < 4; mt++){
                #pragma unroll
                for (int nb = 0; nb < 4; nb++){
                    mma16816(acc[mt][nb*2],   a[mt], b[nb][0], b[nb][2]);
                    mma16816(acc[mt][nb*2+1], a[mt], b[nb][1], b[nb][3]);
                }
            }
        }
        __syncthreads();
    }

    // -------- epilogue: stage fp32 tile in smem, fused coalesced pass ------
    float* Zt = (float*)sm2;         // [128][ZSTR]
    const int rbase = lane >> 2, cpair = (lane & 3)*2;
    #pragma unroll
    for (int mt = 0; mt < 4; mt++){
        int rA = mw0 + mt*16 + rbase;
        int rB = rA + 8;
        #pragma unroll
        for (int nt = 0; nt < 8; nt++){
            int o = o0 + nt*8 + cpair;
            *(float2*)(Zt + rA*ZSTR + o) = make_float2(acc[mt][nt][0], acc[mt][nt][1]);
            *(float2*)(Zt + rB*ZSTR + o) = make_float2(acc[mt][nt][2], acc[mt][nt][3]);
        }
    }
    __syncthreads();
    const int o4 = (tid & 31) * 4;
    #pragma unroll 4
    for (int k = 0; k < 32; k++){
        int r = (tid >> 5) + k*4;
        int m = m0 + r;
        float invn = 1.0f / (0.001f + g_normv[m]);
        float4 v = *(const float4*)(Zt + r*ZSTR + o4);
        float4 z = *(const float4*)(Zraw + (size_t)m*NOUT + o4);
        float4 b4 = *(const float4*)(sbo + o4);
        float4 rr;
        rr.x = (v.x + b4.x)*invn + z.x;
        rr.y = (v.y + b4.y)*invn + z.y;
        rr.z = (v.z + b4.z)*invn + z.z;
        rr.w = (v.w + b4.w)*invn + z.w;
        *(float4*)(out + (size_t)m*NOUT + o4) = rr;
    }
}

// ---------------------------------------------------------------------------
extern "C" void kernel_launch(void* const* d_in, const int* in_sizes, int n_in,
                              void* d_out, int out_size)
{
    const float* M     = (const float*)d_in[0];
    const float* mask  = (const float*)d_in[1];
    const float* Zraw  = (const float*)d_in[2];
    const float* gamma = (const float*)d_in[3];
    const float* beta  = (const float*)d_in[4];
    const float* Wa    = (const float*)d_in[5];
    const float* ba    = (const float*)d_in[6];
    const float* Wb    = (const float*)d_in[7];
    const float* bb    = (const float*)d_in[8];
    const float* Wo    = (const float*)d_in[9];
    const float* bo    = (const float*)d_in[10];
    float* out = (float*)d_out;

    cudaFuncSetAttribute(prep_kernel,  cudaFuncAttributeMaxDynamicSharedMemorySize, PREP_SMEM);
    cudaFuncSetAttribute(gemm1_kernel, cudaFuncAttributeMaxDynamicSharedMemorySize, G1_SMEM);
    cudaFuncSetAttribute(gemm2_kernel, cudaFuncAttributeMaxDynamicSharedMemorySize, G2_SMEM);

    prep_kernel<<<NRES, 256, PREP_SMEM>>>(M, mask, gamma, beta, Wa, ba, Wb, bb);
    norm_kernel<<<NRES, NRES>>>(mask);
    wconv_kernel<<<512, 256>>>(Wo);
    gemm1_kernel<<<dim3(96, 96), 128, G1_SMEM>>>();
    gemm2_kernel<<<NPAIR/128, 128, G2_SMEM>>>(Zraw, bo, out);
}

// round 8
// speedup vs baseline: 1.1207x; 1.1207x over previous
#include <cuda_runtime.h>
#include <cuda_bf16.h>
#include <cstdint>

#define NRES  384
#define NSEQ  256
#define NFEAT 64
#define NPROJ 32
#define NOUT  128
#define ICDIM (NRES*NPROJ)          // 12288
#define NPAIR (NRES*NRES)           // 147456
#define CD    (NPROJ*NPROJ)         // 1024
#define LN_EPS 1e-5f

// ------------------------- scratch (device globals) -------------------------
__device__ __nv_bfloat16 g_Lt[(size_t)ICDIM*NSEQ];   // [m=(i,c)][s]  K-major
__device__ __nv_bfloat16 g_Rt[(size_t)ICDIM*NSEQ];   // [n=(j,d)][s]  K-major
__device__ __nv_bfloat16 g_O [(size_t)NPAIR*CD];     // [(i,j)][(c,d)]
__device__ __nv_bfloat16 g_Wob[NOUT*CD];             // Wo bf16 [o][cd]
__device__ float         g_normv[NPAIR];

// ------------------------- helpers -------------------------
__device__ __forceinline__ uint32_t smem_u32(const void* p){
    uint32_t a;
    asm("{ .reg .u64 t; cvta.to.shared.u64 t, %1; cvt.u32.u64 %0, t; }":"=r"(a):"l"(p));
    return a;
}
__device__ __forceinline__ void ldsm4(uint32_t& r0, uint32_t& r1, uint32_t& r2, uint32_t& r3, uint32_t a){
    asm volatile("ldmatrix.sync.aligned.m8n8.x4.shared.b16 {%0,%1,%2,%3}, [%4];"
        : "=r"(r0),"=r"(r1),"=r"(r2),"=r"(r3) : "r"(a));
}
__device__ __forceinline__ void mma16816(float* c, const uint32_t* a, uint32_t b0, uint32_t b1){
    asm volatile("mma.sync.aligned.m16n8k16.row.col.f32.bf16.bf16.f32 "
        "{%0,%1,%2,%3}, {%4,%5,%6,%7}, {%8,%9}, {%0,%1,%2,%3};"
        : "+f"(c[0]),"+f"(c[1]),"+f"(c[2]),"+f"(c[3])
        : "r"(a[0]),"r"(a[1]),"r"(a[2]),"r"(a[3]),"r"(b0),"r"(b1));
}
__device__ __forceinline__ uint32_t packbf2(float a, float b){
    __nv_bfloat162 h = __floats2bfloat162_rn(a, b);
    return *(uint32_t*)&h;
}
#define CP16(dst, src) asm volatile("cp.async.cg.shared.global [%0], [%1], 16;" \
    :: "r"(dst), "l"(src) : "memory")
#define CP_COMMIT() asm volatile("cp.async.commit_group;" ::: "memory")
#define CP_WAIT(n)  asm volatile("cp.async.wait_group %0;" :: "n"(n) : "memory")

// ---------------------------------------------------------------------------
// prep: LN + projections + mask; write transposed bf16 g_Lt/g_Rt.
// grid=384 (block per residue i), 256 threads (thread per s).
// ---------------------------------------------------------------------------
#define PREP_SMEM (4096*4 + 2*8192*2)   // 49152
__global__ void __launch_bounds__(256,2)
prep_kernel(const float* __restrict__ M, const float* __restrict__ mask,
            const float* __restrict__ gamma, const float* __restrict__ beta,
            const float* __restrict__ Wa, const float* __restrict__ ba,
            const float* __restrict__ Wb, const float* __restrict__ bb)
{
    extern __shared__ float ps[];
    float* sWa = ps;
    float* sWb = ps + 2048;
    __nv_bfloat16* sLb = (__nv_bfloat16*)(ps + 4096);  // [32][256]
    __nv_bfloat16* sRb = sLb + 8192;

    const int i = blockIdx.x;
    const int tid = threadIdx.x;
    for (int u = tid; u < NPROJ*NFEAT; u += 256){ sWa[u] = Wa[u]; sWb[u] = Wb[u]; }

    const int s = tid;
    const float4* mr = (const float4*)(M + ((size_t)s*NRES + i)*NFEAT);
    float4 mn[16];
    float s1 = 0.f, s2 = 0.f;
    #pragma unroll
    for (int q = 0; q < 16; q++){
        float4 v = mr[q]; mn[q] = v;
        s1 += v.x + v.y + v.z + v.w;
        s2 += v.x*v.x + v.y*v.y + v.z*v.z + v.w*v.w;
    }
    float mu  = s1 * (1.f/64.f);
    float var = s2 * (1.f/64.f) - mu*mu;
    float inv = rsqrtf(var + LN_EPS);
    const float4* g4 = (const float4*)gamma;
    const float4* b4 = (const float4*)beta;
    #pragma unroll
    for (int q = 0; q < 16; q++){
        float4 gg = g4[q], be = b4[q];
        mn[q].x = (mn[q].x - mu)*inv*gg.x + be.x;
        mn[q].y = (mn[q].y - mu)*inv*gg.y + be.y;
        mn[q].z = (mn[q].z - mu)*inv*gg.z + be.z;
        mn[q].w = (mn[q].w - mu)*inv*gg.w + be.w;
    }
    const float msk = mask[(size_t)s*NRES + i];
    __syncthreads();

    #pragma unroll 4
    for (int c = 0; c < NPROJ; c++){
        float accA = ba[c], accB = bb[c];
        const float4* wa = (const float4*)(sWa + c*NFEAT);
        const float4* wb = (const float4*)(sWb + c*NFEAT);
        #pragma unroll
        for (int q = 0; q < 16; q++){
            float4 w1 = wa[q], w2 = wb[q], v = mn[q];
            accA += v.x*w1.x + v.y*w1.y + v.z*w1.z + v.w*w1.w;
            accB += v.x*w2.x + v.y*w2.y + v.z*w2.z + v.w*w2.w;
        }
        sLb[c*256 + s] = __float2bfloat16(msk*accA);
        sRb[c*256 + s] = __float2bfloat16(msk*accB);
    }
    __syncthreads();

    for (int u = tid; u < NPROJ*128; u += 256){
        int c = u >> 7, sp = (u & 127) << 1;
        *(uint32_t*)(g_Lt + ((size_t)(i*NPROJ + c))*NSEQ + sp) = *(const uint32_t*)(sLb + c*256 + sp);
        *(uint32_t*)(g_Rt + ((size_t)(i*NPROJ + c))*NSEQ + sp) = *(const uint32_t*)(sRb + c*256 + sp);
    }
}

// ---------------------------------------------------------------------------
__global__ void norm_kernel(const float* __restrict__ mask)
{
    const int i = blockIdx.x, j = threadIdx.x;
    float acc = 0.0f;
    for (int s = 0; s < NSEQ; s++)
        acc += mask[s*NRES + i] * mask[s*NRES + j];
    g_normv[i*NRES + j] = acc;
}

__global__ void wconv_kernel(const float* __restrict__ Wo)
{
    int idx = blockIdx.x*256 + threadIdx.x;
    g_Wob[idx] = __float2bfloat16(Wo[idx]);
}

// ---------------------------------------------------------------------------
// gemm1: O[128x128] = Lt[it*128..] @ Rt[jt*128..]^T, K=256.
// 128 threads, 4 warps, 64x64 warp tiles. 3-stage cp.async ring, occ 2.
// Register-fragment double buffering; smem-staged coalesced epilogue.
// ---------------------------------------------------------------------------
#define G1_SMEM (3*32768)
#define OSTR 136                     // bf16 stride of epilogue tile
__global__ void __launch_bounds__(128,2) gemm1_kernel()
{
    extern __shared__ char sm1[];
    const int tid = threadIdx.x, lane = tid & 31, w = tid >> 5;
    const int it = blockIdx.y, jt = blockIdx.x;
    const int wr = w >> 1, wc = w & 1;
    const int m0 = wr*64, n0 = wc*64;
    const int lo7 = lane & 7, hi = lane >> 4, l15 = lane & 15;

    const uint32_t sb = smem_u32(sm1);
    const int lrb = tid >> 3;        // 0..15
    const int lc  = tid & 7;         // 16B-unit col 0..7

    // hoisted ldsm row offsets
    uint32_t rA[4], rB[4];
    #pragma unroll
    for (int mt = 0; mt < 4; mt++) rA[mt] = (m0 + mt*16 + l15)*128;
    #pragma unroll
    for (int nb = 0; nb < 4; nb++) rB[nb] = (n0 + nb*16 + l15)*128;

    #define G1_LOAD(kc, s) do {                                               \
        _Pragma("unroll")                                                     \
        for (int q = 0; q < 8; q++){                                          \
            int row = q*16 + lrb;                                             \
            int cp = lc ^ (row & 7);                                          \
            uint32_t da = sb + (s)*32768 + row*128 + cp*16;                   \
            CP16(da,         (const void*)(g_Lt + ((size_t)(it*128 + row))*NSEQ + (kc)*64 + lc*8)); \
            CP16(da + 16384, (const void*)(g_Rt + ((size_t)(jt*128 + row))*NSEQ + (kc)*64 + lc*8)); \
        }                                                                     \
    } while(0)

    float acc[4][8][4];
    #pragma unroll
    for (int a = 0; a < 4; a++)
        #pragma unroll
        for (int b = 0; b < 8; b++)
            #pragma unroll
            for (int c = 0; c < 4; c++) acc[a][b][c] = 0.f;

    uint32_t af[2][4][4], bf[2][4][4];

    #define G1_LDFRAG(buf, ch) do {                                           \
        _Pragma("unroll")                                                     \
        for (int mt = 0; mt < 4; mt++)                                        \
            ldsm4(af[buf][mt][0],af[buf][mt][1],af[buf][mt][2],af[buf][mt][3], sA + rA[mt] + (ch)); \
        _Pragma("unroll")                                                     \
        for (int nb = 0; nb < 4; nb++)                                        \
            ldsm4(bf[buf][nb][0],bf[buf][nb][1],bf[buf][nb][2],bf[buf][nb][3], sB + rB[nb] + (ch)); \
    } while(0)

    #define G1_MMA(buf) do {                                                  \
        _Pragma("unroll")                                                     \
        for (int mt = 0; mt < 4; mt++)                                        \
            _Pragma("unroll")                                                 \
            for (int nb = 0; nb < 4; nb++){                                   \
                mma16816(acc[mt][nb*2],   af[buf][mt], bf[buf][nb][0], bf[buf][nb][2]); \
                mma16816(acc[mt][nb*2+1], af[buf][mt], bf[buf][nb][1], bf[buf][nb][3]); \
            }                                                                 \
    } while(0)

    G1_LOAD(0, 0); CP_COMMIT();
    G1_LOAD(1, 1); CP_COMMIT();

    #pragma unroll 1
    for (int kc = 0; kc < 4; kc++){
        if (kc + 2 < 4){ G1_LOAD(kc+2, (kc+2)%3); CP_COMMIT(); CP_WAIT(2); }
        else if (kc + 1 < 4){ CP_WAIT(1); }
        else { CP_WAIT(0); }
        __syncthreads();
        const uint32_t sA = sb + (kc%3)*32768;
        const uint32_t sB = sA + 16384;
        G1_LDFRAG(0, (hi ^ lo7) << 4);
        #pragma unroll
        for (int ks = 0; ks < 4; ks++){
            if (ks < 3){
                int chn = (((ks+1)*2 + hi) ^ lo7) << 4;
                G1_LDFRAG((ks+1)&1, chn);
            }
            G1_MMA(ks&1);
        }
        __syncthreads();
    }

    // -------- epilogue: stage bf16 tile in smem, then coalesced stores -----
    __nv_bfloat16* Ot = (__nv_bfloat16*)sm1;     // [128][OSTR]
    const int rbase = lane >> 2, cpair = (lane & 3)*2;
    #pragma unroll
    for (int mt = 0; mt < 4; mt++){
        int r0 = m0 + mt*16 + rbase;
        int r1 = r0 + 8;
        #pragma unroll
        for (int nt = 0; nt < 8; nt++){
            int col = n0 + nt*8 + cpair;
            *(uint32_t*)(Ot + r0*OSTR + col) = packbf2(acc[mt][nt][0], acc[mt][nt][1]);
            *(uint32_t*)(Ot + r1*OSTR + col) = packbf2(acc[mt][nt][2], acc[mt][nt][3]);
        }
    }
    __syncthreads();
    // 16 pairs, each 1024 bf16 contiguous in g_O
    #pragma unroll 1
    for (int p = 0; p < 16; p++){
        int ri = p >> 2, cj = p & 3;
        size_t gbase = (((size_t)(it*4 + ri)*NRES + jt*4 + cj) << 10);
        int c  = tid >> 2;            // 0..31
        int d8 = (tid & 3) * 8;       // 0,8,16,24
        uint4 v = *(const uint4*)(Ot + (ri*32 + c)*OSTR + cj*32 + d8);
        *(uint4*)(g_O + gbase + c*32 + d8) = v;
    }
}

// ---------------------------------------------------------------------------
// gemm2: Z[m,o] = sum_k O[m,k]*Wob[o,k], m-tile 128, o=128, K=1024.
// 128 threads, 4 warps, 64x64 warp tiles, 3-stage cp.async.
// Register-fragment double buffering; DIRECT fused epilogue (R5 version).
// ---------------------------------------------------------------------------
#define G2_SMEM (3*32768)
__global__ void __launch_bounds__(128,2)
gemm2_kernel(const float* __restrict__ Zraw, const float* __restrict__ bo,
             float* __restrict__ out)
{
    extern __shared__ char sm2[];
    __shared__ float sbo[NOUT];
    const int tid = threadIdx.x, lane = tid & 31, w = tid >> 5;
    const int m0 = blockIdx.x * 128;
    const int wr = w >> 1, wc = w & 1;
    const int mw0 = wr*64, o0 = wc*64;
    const int lo7 = lane & 7, hi = lane >> 4, l15 = lane & 15;

    const uint32_t sb = smem_u32(sm2);
    if (tid < NOUT) sbo[tid] = bo[tid];

    const int lrb = tid >> 3;
    const int lc  = tid & 7;

    uint32_t rA[4], rB[4];
    #pragma unroll
    for (int mt = 0; mt < 4; mt++) rA[mt] = (mw0 + mt*16 + l15)*128;
    #pragma unroll
    for (int nb = 0; nb < 4; nb++) rB[nb] = (o0 + nb*16 + l15)*128;

    #define G2_LOAD(kc, s) do {                                               \
        _Pragma("unroll")                                                     \
        for (int q = 0; q < 8; q++){                                          \
            int row = q*16 + lrb;                                             \
            int cp = lc ^ (row & 7);                                          \
            uint32_t da = sb + (s)*32768 + row*128 + cp*16;                   \
            CP16(da,         (const void*)(g_O   + (size_t)(m0 + row)*CD + (kc)*64 + lc*8)); \
            CP16(da + 16384, (const void*)(g_Wob + (size_t)row*CD        + (kc)*64 + lc*8)); \
        }                                                                     \
    } while(0)

    float acc[4][8][4];
    #pragma unroll
    for (int a = 0; a < 4; a++)
        #pragma unroll
        for (int b = 0; b < 8; b++)
            #pragma unroll
            for (int c = 0; c < 4; c++) acc[a][b][c] = 0.f;

    uint32_t af[2][4][4], bf[2][4][4];

    #define G2_LDFRAG(buf, ch) do {                                           \
        _Pragma("unroll")                                                     \
        for (int mt = 0; mt < 4; mt++)                                        \
            ldsm4(af[buf][mt][0],af[buf][mt][1],af[buf][mt][2],af[buf][mt][3], sA + rA[mt] + (ch)); \
        _Pragma("unroll")                                                     \
        for (int nb = 0; nb < 4; nb++)                                        \
            ldsm4(bf[buf][nb][0],bf[buf][nb][1],bf[buf][nb][2],bf[buf][nb][3], sB + rB[nb] + (ch)); \
    } while(0)

    #define G2_MMA(buf) do {                                                  \
        _Pragma("unroll")                                                     \
        for (int mt = 0; mt < 4; mt++)                                        \
            _Pragma("unroll")                                                 \
            for (int nb = 0; nb < 4; nb++){                                   \
                mma16816(acc[mt][nb*2],   af[buf][mt], bf[buf][nb][0], bf[buf][nb][2]); \
                mma16816(acc[mt][nb*2+1], af[buf][mt], bf[buf][nb][1], bf[buf][nb][3]); \
            }                                                                 \
    } while(0)

    G2_LOAD(0, 0); CP_COMMIT();
    G2_LOAD(1, 1); CP_COMMIT();

    #pragma unroll 1
    for (int kc = 0; kc < 16; kc++){
        if (kc + 2 < 16){ G2_LOAD(kc+2, (kc+2)%3); CP_COMMIT(); CP_WAIT(2); }
        else if (kc + 1 < 16){ CP_WAIT(1); }
        else { CP_WAIT(0); }
        __syncthreads();
        const uint32_t sA = sb + (kc%3)*32768;
        const uint32_t sB = sA + 16384;
        G2_LDFRAG(0, (hi ^ lo7) << 4);
        #pragma unroll
        for (int ks = 0; ks < 4; ks++){
            if (ks < 3){
                int chn = (((ks+1)*2 + hi) ^ lo7) << 4;
                G2_LDFRAG((ks+1)&1, chn);
            }
            G2_MMA(ks&1);
        }
        __syncthreads();
    }

    // direct fused epilogue: (z+bo)*invn + Zraw
    const int rbase = lane >> 2, cpair = (lane & 3)*2;
    #pragma unroll
    for (int mt = 0; mt < 4; mt++){
        int mA = m0 + mw0 + mt*16 + rbase;
        int mB = mA + 8;
        float invA = 1.0f / (0.001f + g_normv[mA]);
        float invB = 1.0f / (0.001f + g_normv[mB]);
        #pragma unroll
        for (int nt = 0; nt < 8; nt++){
            int o = o0 + nt*8 + cpair;
            float b0 = sbo[o], b1 = sbo[o+1];
            float2 zA = *(const float2*)(Zraw + (size_t)mA*NOUT + o);
            float2 zB = *(const float2*)(Zraw + (size_t)mB*NOUT + o);
            float2 rrA, rrB;
            rrA.x = (acc[mt][nt][0] + b0)*invA + zA.x;
            rrA.y = (acc[mt][nt][1] + b1)*invA + zA.y;
            rrB.x = (acc[mt][nt][2] + b0)*invB + zB.x;
            rrB.y = (acc[mt][nt][3] + b1)*invB + zB.y;
            *(float2*)(out + (size_t)mA*NOUT + o) = rrA;
            *(float2*)(out + (size_t)mB*NOUT + o) = rrB;
        }
    }
}

// ---------------------------------------------------------------------------
extern "C" void kernel_launch(void* const* d_in, const int* in_sizes, int n_in,
                              void* d_out, int out_size)
{
    const float* M     = (const float*)d_in[0];
    const float* mask  = (const float*)d_in[1];
    const float* Zraw  = (const float*)d_in[2];
    const float* gamma = (const float*)d_in[3];
    const float* beta  = (const float*)d_in[4];
    const float* Wa    = (const float*)d_in[5];
    const float* ba    = (const float*)d_in[6];
    const float* Wb    = (const float*)d_in[7];
    const float* bb    = (const float*)d_in[8];
    const float* Wo    = (const float*)d_in[9];
    const float* bo    = (const float*)d_in[10];
    float* out = (float*)d_out;

    cudaFuncSetAttribute(prep_kernel,  cudaFuncAttributeMaxDynamicSharedMemorySize, PREP_SMEM);
    cudaFuncSetAttribute(gemm1_kernel, cudaFuncAttributeMaxDynamicSharedMemorySize, G1_SMEM);
    cudaFuncSetAttribute(gemm2_kernel, cudaFuncAttributeMaxDynamicSharedMemorySize, G2_SMEM);

    prep_kernel<<<NRES, 256, PREP_SMEM>>>(M, mask, gamma, beta, Wa, ba, Wb, bb);
    norm_kernel<<<NRES, NRES>>>(mask);
    wconv_kernel<<<512, 256>>>(Wo);
    gemm1_kernel<<<dim3(96, 96), 128, G1_SMEM>>>();
    gemm2_kernel<<<NPAIR/128, 128, G2_SMEM>>>(Zraw, bo, out);
}

// round 9
// speedup vs baseline: 1.2182x; 1.0870x over previous
#include <cuda_runtime.h>
#include <cuda_fp16.h>
#include <cstdint>

#define NRES  384
#define NSEQ  256
#define NFEAT 64
#define NPROJ 32
#define NOUT  128
#define ICDIM (NRES*NPROJ)          // 12288
#define NPAIR (NRES*NRES)           // 147456
#define CD    (NPROJ*NPROJ)         // 1024
#define LN_EPS 1e-5f

// ------------------------- scratch (device globals) -------------------------
__device__ __half g_Lt[(size_t)ICDIM*NSEQ];   // [m=(i,c)][s]  K-major fp16
__device__ __half g_Rt[(size_t)ICDIM*NSEQ];   // [n=(j,d)][s]  K-major fp16
__device__ __half g_O [(size_t)NPAIR*CD];     // [(i,j)][(c,d)] fp16
__device__ __half g_Wob[NOUT*CD];             // Wo fp16 [o][cd]
__device__ float  g_normv[NPAIR];

// ------------------------- helpers -------------------------
__device__ __forceinline__ uint32_t smem_u32(const void* p){
    uint32_t a;
    asm("{ .reg .u64 t; cvta.to.shared.u64 t, %1; cvt.u32.u64 %0, t; }":"=r"(a):"l"(p));
    return a;
}
__device__ __forceinline__ void ldsm4(uint32_t& r0, uint32_t& r1, uint32_t& r2, uint32_t& r3, uint32_t a){
    asm volatile("ldmatrix.sync.aligned.m8n8.x4.shared.b16 {%0,%1,%2,%3}, [%4];"
        : "=r"(r0),"=r"(r1),"=r"(r2),"=r"(r3) : "r"(a));
}
// fp32-accum fp16-input MMA (gemm2)
__device__ __forceinline__ void mma16816f(float* c, const uint32_t* a, uint32_t b0, uint32_t b1){
    asm volatile("mma.sync.aligned.m16n8k16.row.col.f32.f16.f16.f32 "
        "{%0,%1,%2,%3}, {%4,%5,%6,%7}, {%8,%9}, {%0,%1,%2,%3};"
        : "+f"(c[0]),"+f"(c[1]),"+f"(c[2]),"+f"(c[3])
        : "r"(a[0]),"r"(a[1]),"r"(a[2]),"r"(a[3]),"r"(b0),"r"(b1));
}
// fp16-accum MMA (gemm1): D packed as 2x f16x2
__device__ __forceinline__ void mma16816h(uint32_t* d, const uint32_t* a, uint32_t b0, uint32_t b1){
    asm volatile("mma.sync.aligned.m16n8k16.row.col.f16.f16.f16.f16 "
        "{%0,%1}, {%2,%3,%4,%5}, {%6,%7}, {%0,%1};"
        : "+r"(d[0]),"+r"(d[1])
        : "r"(a[0]),"r"(a[1]),"r"(a[2]),"r"(a[3]),"r"(b0),"r"(b1));
}
#define CP16(dst, src) asm volatile("cp.async.cg.shared.global [%0], [%1], 16;" \
    :: "r"(dst), "l"(src) : "memory")
#define CP_COMMIT() asm volatile("cp.async.commit_group;" ::: "memory")
#define CP_WAIT(n)  asm volatile("cp.async.wait_group %0;" :: "n"(n) : "memory")

// ---------------------------------------------------------------------------
// prep: LN + projections + mask; write transposed fp16 g_Lt/g_Rt.
// grid=384 (block per residue i), 256 threads (thread per s).
// ---------------------------------------------------------------------------
#define PREP_SMEM (4096*4 + 2*8192*2)   // 49152
__global__ void __launch_bounds__(256,2)
prep_kernel(const float* __restrict__ M, const float* __restrict__ mask,
            const float* __restrict__ gamma, const float* __restrict__ beta,
            const float* __restrict__ Wa, const float* __restrict__ ba,
            const float* __restrict__ Wb, const float* __restrict__ bb)
{
    extern __shared__ float ps[];
    float* sWa = ps;
    float* sWb = ps + 2048;
    __half* sLb = (__half*)(ps + 4096);  // [32][256]
    __half* sRb = sLb + 8192;

    const int i = blockIdx.x;
    const int tid = threadIdx.x;
    for (int u = tid; u < NPROJ*NFEAT; u += 256){ sWa[u] = Wa[u]; sWb[u] = Wb[u]; }

    const int s = tid;
    const float4* mr = (const float4*)(M + ((size_t)s*NRES + i)*NFEAT);
    float4 mn[16];
    float s1 = 0.f, s2 = 0.f;
    #pragma unroll
    for (int q = 0; q < 16; q++){
        float4 v = mr[q]; mn[q] = v;
        s1 += v.x + v.y + v.z + v.w;
        s2 += v.x*v.x + v.y*v.y + v.z*v.z + v.w*v.w;
    }
    float mu  = s1 * (1.f/64.f);
    float var = s2 * (1.f/64.f) - mu*mu;
    float inv = rsqrtf(var + LN_EPS);
    const float4* g4 = (const float4*)gamma;
    const float4* b4 = (const float4*)beta;
    #pragma unroll
    for (int q = 0; q < 16; q++){
        float4 gg = g4[q], be = b4[q];
        mn[q].x = (mn[q].x - mu)*inv*gg.x + be.x;
        mn[q].y = (mn[q].y - mu)*inv*gg.y + be.y;
        mn[q].z = (mn[q].z - mu)*inv*gg.z + be.z;
        mn[q].w = (mn[q].w - mu)*inv*gg.w + be.w;
    }
    const float msk = mask[(size_t)s*NRES + i];
    __syncthreads();

    #pragma unroll 4
    for (int c = 0; c < NPROJ; c++){
        float accA = ba[c], accB = bb[c];
        const float4* wa = (const float4*)(sWa + c*NFEAT);
        const float4* wb = (const float4*)(sWb + c*NFEAT);
        #pragma unroll
        for (int q = 0; q < 16; q++){
            float4 w1 = wa[q], w2 = wb[q], v = mn[q];
            accA += v.x*w1.x + v.y*w1.y + v.z*w1.z + v.w*w1.w;
            accB += v.x*w2.x + v.y*w2.y + v.z*w2.z + v.w*w2.w;
        }
        sLb[c*256 + s] = __float2half(msk*accA);
        sRb[c*256 + s] = __float2half(msk*accB);
    }
    __syncthreads();

    for (int u = tid; u < NPROJ*128; u += 256){
        int c = u >> 7, sp = (u & 127) << 1;
        *(uint32_t*)(g_Lt + ((size_t)(i*NPROJ + c))*NSEQ + sp) = *(const uint32_t*)(sLb + c*256 + sp);
        *(uint32_t*)(g_Rt + ((size_t)(i*NPROJ + c))*NSEQ + sp) = *(const uint32_t*)(sRb + c*256 + sp);
    }
}

// ---------------------------------------------------------------------------
__global__ void norm_kernel(const float* __restrict__ mask)
{
    const int i = blockIdx.x, j = threadIdx.x;
    float acc = 0.0f;
    for (int s = 0; s < NSEQ; s++)
        acc += mask[s*NRES + i] * mask[s*NRES + j];
    g_normv[i*NRES + j] = acc;
}

__global__ void wconv_kernel(const float* __restrict__ Wo)
{
    int idx = blockIdx.x*256 + threadIdx.x;
    g_Wob[idx] = __float2half(Wo[idx]);
}

// ---------------------------------------------------------------------------
// gemm1: O[128x128] = Lt[it*128..] @ Rt[jt*128..]^T, K=256, fp16 accum.
// 128 threads, 4 warps, 64x64 warp tiles. 2-stage cp.async ring (64KB), occ 3.
// Smem-staged coalesced epilogue.
// ---------------------------------------------------------------------------
#define G1_SMEM (2*32768)
#define OSTR 136                     // fp16 stride of epilogue tile
__global__ void __launch_bounds__(128,3) gemm1_kernel()
{
    extern __shared__ char sm1[];
    const int tid = threadIdx.x, lane = tid & 31, w = tid >> 5;
    const int it = blockIdx.y, jt = blockIdx.x;
    const int wr = w >> 1, wc = w & 1;
    const int m0 = wr*64, n0 = wc*64;
    const int lo7 = lane & 7, hi = lane >> 4, l15 = lane & 15;

    const uint32_t sb = smem_u32(sm1);
    const int lrb = tid >> 3;        // 0..15
    const int lc  = tid & 7;         // 16B-unit col 0..7

    uint32_t rA[4], rB[4];
    #pragma unroll
    for (int mt = 0; mt < 4; mt++) rA[mt] = (m0 + mt*16 + l15)*128;
    #pragma unroll
    for (int nb = 0; nb < 4; nb++) rB[nb] = (n0 + nb*16 + l15)*128;

    #define G1_LOAD(kc, s) do {                                               \
        _Pragma("unroll")                                                     \
        for (int q = 0; q < 8; q++){                                          \
            int row = q*16 + lrb;                                             \
            int cp = lc ^ (row & 7);                                          \
            uint32_t da = sb + (s)*32768 + row*128 + cp*16;                   \
            CP16(da,         (const void*)(g_Lt + ((size_t)(it*128 + row))*NSEQ + (kc)*64 + lc*8)); \
            CP16(da + 16384, (const void*)(g_Rt + ((size_t)(jt*128 + row))*NSEQ + (kc)*64 + lc*8)); \
        }                                                                     \
    } while(0)

    uint32_t hacc[4][8][2];
    #pragma unroll
    for (int a = 0; a < 4; a++)
        #pragma unroll
        for (int b = 0; b < 8; b++){ hacc[a][b][0] = 0u; hacc[a][b][1] = 0u; }

    uint32_t af[2][4][4], bf[2][4][4];

    #define G1_LDFRAG(buf, ch) do {                                           \
        _Pragma("unroll")                                                     \
        for (int mt = 0; mt < 4; mt++)                                        \
            ldsm4(af[buf][mt][0],af[buf][mt][1],af[buf][mt][2],af[buf][mt][3], sA + rA[mt] + (ch)); \
        _Pragma("unroll")                                                     \
        for (int nb = 0; nb < 4; nb++)                                        \
            ldsm4(bf[buf][nb][0],bf[buf][nb][1],bf[buf][nb][2],bf[buf][nb][3], sB + rB[nb] + (ch)); \
    } while(0)

    #define G1_MMA(buf) do {                                                  \
        _Pragma("unroll")                                                     \
        for (int mt = 0; mt < 4; mt++)                                        \
            _Pragma("unroll")                                                 \
            for (int nb = 0; nb < 4; nb++){                                   \
                mma16816h(hacc[mt][nb*2],   af[buf][mt], bf[buf][nb][0], bf[buf][nb][2]); \
                mma16816h(hacc[mt][nb*2+1], af[buf][mt], bf[buf][nb][1], bf[buf][nb][3]); \
            }                                                                 \
    } while(0)

    G1_LOAD(0, 0); CP_COMMIT();

    #pragma unroll 1
    for (int kc = 0; kc < 4; kc++){
        if (kc + 1 < 4){ G1_LOAD(kc+1, (kc+1)&1); CP_COMMIT(); CP_WAIT(1); }
        else { CP_WAIT(0); }
        __syncthreads();
        const uint32_t sA = sb + (kc&1)*32768;
        const uint32_t sB = sA + 16384;
        G1_LDFRAG(0, (hi ^ lo7) << 4);
        #pragma unroll
        for (int ks = 0; ks < 4; ks++){
            if (ks < 3){
                int chn = (((ks+1)*2 + hi) ^ lo7) << 4;
                G1_LDFRAG((ks+1)&1, chn);
            }
            G1_MMA(ks&1);
        }
        __syncthreads();
    }

    // -------- epilogue: stage fp16 tile in smem, then coalesced stores -----
    __half* Ot = (__half*)sm1;       // [128][OSTR]
    const int rbase = lane >> 2, cpair = (lane & 3)*2;
    #pragma unroll
    for (int mt = 0; mt < 4; mt++){
        int r0 = m0 + mt*16 + rbase;
        int r1 = r0 + 8;
        #pragma unroll
        for (int nt = 0; nt < 8; nt++){
            int col = n0 + nt*8 + cpair;
            *(uint32_t*)(Ot + r0*OSTR + col) = hacc[mt][nt][0];
            *(uint32_t*)(Ot + r1*OSTR + col) = hacc[mt][nt][1];
        }
    }
    __syncthreads();
    // 16 pairs, each 1024 fp16 contiguous in g_O
    #pragma unroll 1
    for (int p = 0; p < 16; p++){
        int ri = p >> 2, cj = p & 3;
        size_t gbase = (((size_t)(it*4 + ri)*NRES + jt*4 + cj) << 10);
        int c  = tid >> 2;            // 0..31
        int d8 = (tid & 3) * 8;       // 0,8,16,24
        uint4 v = *(const uint4*)(Ot + (ri*32 + c)*OSTR + cj*32 + d8);
        *(uint4*)(g_O + gbase + c*32 + d8) = v;
    }
}

// ---------------------------------------------------------------------------
// gemm2: Z[m,o] = sum_k O[m,k]*Wob[o,k], m-tile 128, o=128, K=1024, fp32 acc.
// 128 threads, 4 warps, 64x64 warp tiles, 3-stage cp.async. Direct epilogue.
// ---------------------------------------------------------------------------
#define G2_SMEM (3*32768)
__global__ void __launch_bounds__(128,2)
gemm2_kernel(const float* __restrict__ Zraw, const float* __restrict__ bo,
             float* __restrict__ out)
{
    extern __shared__ char sm2[];
    __shared__ float sbo[NOUT];
    const int tid = threadIdx.x, lane = tid & 31, w = tid >> 5;
    const int m0 = blockIdx.x * 128;
    const int wr = w >> 1, wc = w & 1;
    const int mw0 = wr*64, o0 = wc*64;
    const int lo7 = lane & 7, hi = lane >> 4, l15 = lane & 15;

    const uint32_t sb = smem_u32(sm2);
    if (tid < NOUT) sbo[tid] = bo[tid];

    const int lrb = tid >> 3;
    const int lc  = tid & 7;

    uint32_t rA[4], rB[4];
    #pragma unroll
    for (int mt = 0; mt < 4; mt++) rA[mt] = (mw0 + mt*16 + l15)*128;
    #pragma unroll
    for (int nb = 0; nb < 4; nb++) rB[nb] = (o0 + nb*16 + l15)*128;

    #define G2_LOAD(kc, s) do {                                               \
        _Pragma("unroll")                                                     \
        for (int q = 0; q < 8; q++){                                          \
            int row = q*16 + lrb;                                             \
            int cp = lc ^ (row & 7);                                          \
            uint32_t da = sb + (s)*32768 + row*128 + cp*16;                   \
            CP16(da,         (const void*)(g_O   + (size_t)(m0 + row)*CD + (kc)*64 + lc*8)); \
            CP16(da + 16384, (const void*)(g_Wob + (size_t)row*CD        + (kc)*64 + lc*8)); \
        }                                                                     \
    } while(0)

    float acc[4][8][4];
    #pragma unroll
    for (int a = 0; a < 4; a++)
        #pragma unroll
        for (int b = 0; b < 8; b++)
            #pragma unroll
            for (int c = 0; c < 4; c++) acc[a][b][c] = 0.f;

    uint32_t af[2][4][4], bf[2][4][4];

    #define G2_LDFRAG(buf, ch) do {                                           \
        _Pragma("unroll")                                                     \
        for (int mt = 0; mt < 4; mt++)                                        \
            ldsm4(af[buf][mt][0],af[buf][mt][1],af[buf][mt][2],af[buf][mt][3], sA + rA[mt] + (ch)); \
        _Pragma("unroll")                                                     \
        for (int nb = 0; nb < 4; nb++)                                        \
            ldsm4(bf[buf][nb][0],bf[buf][nb][1],bf[buf][nb][2],bf[buf][nb][3], sB + rB[nb] + (ch)); \
    } while(0)

    #define G2_MMA(buf) do {                                                  \
        _Pragma("unroll")                                                     \
        for (int mt = 0; mt < 4; mt++)                                        \
            _Pragma("unroll")                                                 \
            for (int nb = 0; nb < 4; nb++){                                   \
                mma16816f(acc[mt][nb*2],   af[buf][mt], bf[buf][nb][0], bf[buf][nb][2]); \
                mma16816f(acc[mt][nb*2+1], af[buf][mt], bf[buf][nb][1], bf[buf][nb][3]); \
            }                                                                 \
    } while(0)

    G2_LOAD(0, 0); CP_COMMIT();
    G2_LOAD(1, 1); CP_COMMIT();

    #pragma unroll 1
    for (int kc = 0; kc < 16; kc++){
        if (kc + 2 < 16){ G2_LOAD(kc+2, (kc+2)%3); CP_COMMIT(); CP_WAIT(2); }
        else if (kc + 1 < 16){ CP_WAIT(1); }
        else { CP_WAIT(0); }
        __syncthreads();
        const uint32_t sA = sb + (kc%3)*32768;
        const uint32_t sB = sA + 16384;
        G2_LDFRAG(0, (hi ^ lo7) << 4);
        #pragma unroll
        for (int ks = 0; ks < 4; ks++){
            if (ks < 3){
                int chn = (((ks+1)*2 + hi) ^ lo7) << 4;
                G2_LDFRAG((ks+1)&1, chn);
            }
            G2_MMA(ks&1);
        }
        __syncthreads();
    }

    // direct fused epilogue: (z+bo)*invn + Zraw
    const int rbase = lane >> 2, cpair = (lane & 3)*2;
    #pragma unroll
    for (int mt = 0; mt < 4; mt++){
        int mA = m0 + mw0 + mt*16 + rbase;
        int mB = mA + 8;
        float invA = 1.0f / (0.001f + g_normv[mA]);
        float invB = 1.0f / (0.001f + g_normv[mB]);
        #pragma unroll
        for (int nt = 0; nt < 8; nt++){
            int o = o0 + nt*8 + cpair;
            float b0 = sbo[o], b1 = sbo[o+1];
            float2 zA = *(const float2*)(Zraw + (size_t)mA*NOUT + o);
            float2 zB = *(const float2*)(Zraw + (size_t)mB*NOUT + o);
            float2 rrA, rrB;
            rrA.x = (acc[mt][nt][0] + b0)*invA + zA.x;
            rrA.y = (acc[mt][nt][1] + b1)*invA + zA.y;
            rrB.x = (acc[mt][nt][2] + b0)*invB + zB.x;
            rrB.y = (acc[mt][nt][3] + b1)*invB + zB.y;
            *(float2*)(out + (size_t)mA*NOUT + o) = rrA;
            *(float2*)(out + (size_t)mB*NOUT + o) = rrB;
        }
    }
}

// ---------------------------------------------------------------------------
extern "C" void kernel_launch(void* const* d_in, const int* in_sizes, int n_in,
                              void* d_out, int out_size)
{
    const float* M     = (const float*)d_in[0];
    const float* mask  = (const float*)d_in[1];
    const float* Zraw  = (const float*)d_in[2];
    const float* gamma = (const float*)d_in[3];
    const float* beta  = (const float*)d_in[4];
    const float* Wa    = (const float*)d_in[5];
    const float* ba    = (const float*)d_in[6];
    const float* Wb    = (const float*)d_in[7];
    const float* bb    = (const float*)d_in[8];
    const float* Wo    = (const float*)d_in[9];
    const float* bo    = (const float*)d_in[10];
    float* out = (float*)d_out;

    cudaFuncSetAttribute(prep_kernel,  cudaFuncAttributeMaxDynamicSharedMemorySize, PREP_SMEM);
    cudaFuncSetAttribute(gemm1_kernel, cudaFuncAttributeMaxDynamicSharedMemorySize, G1_SMEM);
    cudaFuncSetAttribute(gemm2_kernel, cudaFuncAttributeMaxDynamicSharedMemorySize, G2_SMEM);

    prep_kernel<<<NRES, 256, PREP_SMEM>>>(M, mask, gamma, beta, Wa, ba, Wb, bb);
    norm_kernel<<<NRES, NRES>>>(mask);
    wconv_kernel<<<512, 256>>>(Wo);
    gemm1_kernel<<<dim3(96, 96), 128, G1_SMEM>>>();
    gemm2_kernel<<<NPAIR/128, 128, G2_SMEM>>>(Zraw, bo, out);
}

// round 10
// speedup vs baseline: 1.2814x; 1.0519x over previous
#include <cuda_runtime.h>
#include <cuda_fp16.h>
#include <cstdint>

#define NRES  384
#define NSEQ  256
#define NFEAT 64
#define NPROJ 32
#define NOUT  128
#define ICDIM (NRES*NPROJ)          // 12288
#define NPAIR (NRES*NRES)           // 147456
#define CD    (NPROJ*NPROJ)         // 1024
#define LN_EPS 1e-5f

// ------------------------- scratch (device globals) -------------------------
__device__ __half g_Lt[(size_t)ICDIM*NSEQ];   // [m=(i,c)][s]  K-major fp16
__device__ __half g_Rt[(size_t)ICDIM*NSEQ];   // [n=(j,d)][s]  K-major fp16
__device__ __half g_O [(size_t)NPAIR*CD];     // [(i,j)][(c,d)] fp16
__device__ __half g_Wob[NOUT*CD];             // Wo fp16 [o][cd]
__device__ float  g_normv[NPAIR];

// ------------------------- helpers -------------------------
__device__ __forceinline__ uint32_t smem_u32(const void* p){
    uint32_t a;
    asm("{ .reg .u64 t; cvta.to.shared.u64 t, %1; cvt.u32.u64 %0, t; }":"=r"(a):"l"(p));
    return a;
}
__device__ __forceinline__ void ldsm4(uint32_t& r0, uint32_t& r1, uint32_t& r2, uint32_t& r3, uint32_t a){
    asm volatile("ldmatrix.sync.aligned.m8n8.x4.shared.b16 {%0,%1,%2,%3}, [%4];"
        : "=r"(r0),"=r"(r1),"=r"(r2),"=r"(r3) : "r"(a));
}
// fp16-accum MMA: D packed as 2x f16x2
__device__ __forceinline__ void mma16816h(uint32_t* d, const uint32_t* a, uint32_t b0, uint32_t b1){
    asm volatile("mma.sync.aligned.m16n8k16.row.col.f16.f16.f16.f16 "
        "{%0,%1}, {%2,%3,%4,%5}, {%6,%7}, {%0,%1};"
        : "+r"(d[0]),"+r"(d[1])
        : "r"(a[0]),"r"(a[1]),"r"(a[2]),"r"(a[3]),"r"(b0),"r"(b1));
}
#define CP16(dst, src) asm volatile("cp.async.cg.shared.global [%0], [%1], 16;" \
    :: "r"(dst), "l"(src) : "memory")
#define CP_COMMIT() asm volatile("cp.async.commit_group;" ::: "memory")
#define CP_WAIT(n)  asm volatile("cp.async.wait_group %0;" :: "n"(n) : "memory")

// ---------------------------------------------------------------------------
// prep: LN + projections + mask; write transposed fp16 g_Lt/g_Rt.
// grid=384 (block per residue i), 256 threads (thread per s).
// ---------------------------------------------------------------------------
#define PREP_SMEM (4096*4 + 2*8192*2)   // 49152
__global__ void __launch_bounds__(256,2)
prep_kernel(const float* __restrict__ M, const float* __restrict__ mask,
            const float* __restrict__ gamma, const float* __restrict__ beta,
            const float* __restrict__ Wa, const float* __restrict__ ba,
            const float* __restrict__ Wb, const float* __restrict__ bb)
{
    extern __shared__ float ps[];
    float* sWa = ps;
    float* sWb = ps + 2048;
    __half* sLb = (__half*)(ps + 4096);  // [32][256]
    __half* sRb = sLb + 8192;

    const int i = blockIdx.x;
    const int tid = threadIdx.x;
    for (int u = tid; u < NPROJ*NFEAT; u += 256){ sWa[u] = Wa[u]; sWb[u] = Wb[u]; }

    const int s = tid;
    const float4* mr = (const float4*)(M + ((size_t)s*NRES + i)*NFEAT);
    float4 mn[16];
    float s1 = 0.f, s2 = 0.f;
    #pragma unroll
    for (int q = 0; q < 16; q++){
        float4 v = mr[q]; mn[q] = v;
        s1 += v.x + v.y + v.z + v.w;
        s2 += v.x*v.x + v.y*v.y + v.z*v.z + v.w*v.w;
    }
    float mu  = s1 * (1.f/64.f);
    float var = s2 * (1.f/64.f) - mu*mu;
    float inv = rsqrtf(var + LN_EPS);
    const float4* g4 = (const float4*)gamma;
    const float4* b4 = (const float4*)beta;
    #pragma unroll
    for (int q = 0; q < 16; q++){
        float4 gg = g4[q], be = b4[q];
        mn[q].x = (mn[q].x - mu)*inv*gg.x + be.x;
        mn[q].y = (mn[q].y - mu)*inv*gg.y + be.y;
        mn[q].z = (mn[q].z - mu)*inv*gg.z + be.z;
        mn[q].w = (mn[q].w - mu)*inv*gg.w + be.w;
    }
    const float msk = mask[(size_t)s*NRES + i];
    __syncthreads();

    #pragma unroll 4
    for (int c = 0; c < NPROJ; c++){
        float accA = ba[c], accB = bb[c];
        const float4* wa = (const float4*)(sWa + c*NFEAT);
        const float4* wb = (const float4*)(sWb + c*NFEAT);
        #pragma unroll
        for (int q = 0; q < 16; q++){
            float4 w1 = wa[q], w2 = wb[q], v = mn[q];
            accA += v.x*w1.x + v.y*w1.y + v.z*w1.z + v.w*w1.w;
            accB += v.x*w2.x + v.y*w2.y + v.z*w2.z + v.w*w2.w;
        }
        sLb[c*256 + s] = __float2half(msk*accA);
        sRb[c*256 + s] = __float2half(msk*accB);
    }
    __syncthreads();

    for (int u = tid; u < NPROJ*128; u += 256){
        int c = u >> 7, sp = (u & 127) << 1;
        *(uint32_t*)(g_Lt + ((size_t)(i*NPROJ + c))*NSEQ + sp) = *(const uint32_t*)(sLb + c*256 + sp);
        *(uint32_t*)(g_Rt + ((size_t)(i*NPROJ + c))*NSEQ + sp) = *(const uint32_t*)(sRb + c*256 + sp);
    }
}

// ---------------------------------------------------------------------------
__global__ void norm_kernel(const float* __restrict__ mask)
{
    const int i = blockIdx.x, j = threadIdx.x;
    float acc = 0.0f;
    for (int s = 0; s < NSEQ; s++)
        acc += mask[s*NRES + i] * mask[s*NRES + j];
    g_normv[i*NRES + j] = acc;
}

__global__ void wconv_kernel(const float* __restrict__ Wo)
{
    int idx = blockIdx.x*256 + threadIdx.x;
    g_Wob[idx] = __float2half(Wo[idx]);
}

// ---------------------------------------------------------------------------
// gemm1: O[128x128] = Lt[it*128..] @ Rt[jt*128..]^T, K=256, fp16 accum.
// 128 threads, 4 warps, 64x64 warp tiles. 2-stage cp.async ring (64KB), occ 3.
// Smem-staged coalesced epilogue.
// ---------------------------------------------------------------------------
#define G1_SMEM (2*32768)
#define OSTR 136                     // fp16 stride of epilogue tile
__global__ void __launch_bounds__(128,3) gemm1_kernel()
{
    extern __shared__ char sm1[];
    const int tid = threadIdx.x, lane = tid & 31, w = tid >> 5;
    const int it = blockIdx.y, jt = blockIdx.x;
    const int wr = w >> 1, wc = w & 1;
    const int m0 = wr*64, n0 = wc*64;
    const int lo7 = lane & 7, hi = lane >> 4, l15 = lane & 15;

    const uint32_t sb = smem_u32(sm1);
    const int lrb = tid >> 3;        // 0..15
    const int lc  = tid & 7;         // 16B-unit col 0..7

    uint32_t rA[4], rB[4];
    #pragma unroll
    for (int mt = 0; mt < 4; mt++) rA[mt] = (m0 + mt*16 + l15)*128;
    #pragma unroll
    for (int nb = 0; nb < 4; nb++) rB[nb] = (n0 + nb*16 + l15)*128;

    #define G1_LOAD(kc, s) do {                                               \
        _Pragma("unroll")                                                     \
        for (int q = 0; q < 8; q++){                                          \
            int row = q*16 + lrb;                                             \
            int cp = lc ^ (row & 7);                                          \
            uint32_t da = sb + (s)*32768 + row*128 + cp*16;                   \
            CP16(da,         (const void*)(g_Lt + ((size_t)(it*128 + row))*NSEQ + (kc)*64 + lc*8)); \
            CP16(da + 16384, (const void*)(g_Rt + ((size_t)(jt*128 + row))*NSEQ + (kc)*64 + lc*8)); \
        }                                                                     \
    } while(0)

    uint32_t hacc[4][8][2];
    #pragma unroll
    for (int a = 0; a < 4; a++)
        #pragma unroll
        for (int b = 0; b < 8; b++){ hacc[a][b][0] = 0u; hacc[a][b][1] = 0u; }

    uint32_t af[2][4][4], bf[2][4][4];

    #define G1_LDFRAG(buf, ch) do {                                           \
        _Pragma("unroll")                                                     \
        for (int mt = 0; mt < 4; mt++)                                        \
            ldsm4(af[buf][mt][0],af[buf][mt][1],af[buf][mt][2],af[buf][mt][3], sA + rA[mt] + (ch)); \
        _Pragma("unroll")                                                     \
        for (int nb = 0; nb < 4; nb++)                                        \
            ldsm4(bf[buf][nb][0],bf[buf][nb][1],bf[buf][nb][2],bf[buf][nb][3], sB + rB[nb] + (ch)); \
    } while(0)

    #define G1_MMA(buf) do {                                                  \
        _Pragma("unroll")                                                     \
        for (int mt = 0; mt < 4; mt++)                                        \
            _Pragma("unroll")                                                 \
            for (int nb = 0; nb < 4; nb++){                                   \
                mma16816h(hacc[mt][nb*2],   af[buf][mt], bf[buf][nb][0], bf[buf][nb][2]); \
                mma16816h(hacc[mt][nb*2+1], af[buf][mt], bf[buf][nb][1], bf[buf][nb][3]); \
            }                                                                 \
    } while(0)

    G1_LOAD(0, 0); CP_COMMIT();

    #pragma unroll 1
    for (int kc = 0; kc < 4; kc++){
        if (kc + 1 < 4){ G1_LOAD(kc+1, (kc+1)&1); CP_COMMIT(); CP_WAIT(1); }
        else { CP_WAIT(0); }
        __syncthreads();
        const uint32_t sA = sb + (kc&1)*32768;
        const uint32_t sB = sA + 16384;
        G1_LDFRAG(0, (hi ^ lo7) << 4);
        #pragma unroll
        for (int ks = 0; ks < 4; ks++){
            if (ks < 3){
                int chn = (((ks+1)*2 + hi) ^ lo7) << 4;
                G1_LDFRAG((ks+1)&1, chn);
            }
            G1_MMA(ks&1);
        }
        __syncthreads();
    }

    // -------- epilogue: stage fp16 tile in smem, then coalesced stores -----
    __half* Ot = (__half*)sm1;       // [128][OSTR]
    const int rbase = lane >> 2, cpair = (lane & 3)*2;
    #pragma unroll
    for (int mt = 0; mt < 4; mt++){
        int r0 = m0 + mt*16 + rbase;
        int r1 = r0 + 8;
        #pragma unroll
        for (int nt = 0; nt < 8; nt++){
            int col = n0 + nt*8 + cpair;
            *(uint32_t*)(Ot + r0*OSTR + col) = hacc[mt][nt][0];
            *(uint32_t*)(Ot + r1*OSTR + col) = hacc[mt][nt][1];
        }
    }
    __syncthreads();
    // 16 pairs, each 1024 fp16 contiguous in g_O
    #pragma unroll 1
    for (int p = 0; p < 16; p++){
        int ri = p >> 2, cj = p & 3;
        size_t gbase = (((size_t)(it*4 + ri)*NRES + jt*4 + cj) << 10);
        int c  = tid >> 2;            // 0..31
        int d8 = (tid & 3) * 8;       // 0,8,16,24
        uint4 v = *(const uint4*)(Ot + (ri*32 + c)*OSTR + cj*32 + d8);
        *(uint4*)(g_O + gbase + c*32 + d8) = v;
    }
}

// ---------------------------------------------------------------------------
// gemm2: Z[m,o] = sum_k O[m,k]*Wob[o,k], m-tile 128, o=128, K=1024, fp16 acc.
// 128 threads, 4 warps, 64x64 warp tiles, 2-stage cp.async (64KB), occ 3.
// Direct fused epilogue.
// ---------------------------------------------------------------------------
#define G2_SMEM (2*32768)
__global__ void __launch_bounds__(128,3)
gemm2_kernel(const float* __restrict__ Zraw, const float* __restrict__ bo,
             float* __restrict__ out)
{
    extern __shared__ char sm2[];
    __shared__ float sbo[NOUT];
    const int tid = threadIdx.x, lane = tid & 31, w = tid >> 5;
    const int m0 = blockIdx.x * 128;
    const int wr = w >> 1, wc = w & 1;
    const int mw0 = wr*64, o0 = wc*64;
    const int lo7 = lane & 7, hi = lane >> 4, l15 = lane & 15;

    const uint32_t sb = smem_u32(sm2);
    if (tid < NOUT) sbo[tid] = bo[tid];

    const int lrb = tid >> 3;
    const int lc  = tid & 7;

    uint32_t rA[4], rB[4];
    #pragma unroll
    for (int mt = 0; mt < 4; mt++) rA[mt] = (mw0 + mt*16 + l15)*128;
    #pragma unroll
    for (int nb = 0; nb < 4; nb++) rB[nb] = (o0 + nb*16 + l15)*128;

    #define G2_LOAD(kc, s) do {                                               \
        _Pragma("unroll")                                                     \
        for (int q = 0; q < 8; q++){                                          \
            int row = q*16 + lrb;                                             \
            int cp = lc ^ (row & 7);                                          \
            uint32_t da = sb + (s)*32768 + row*128 + cp*16;                   \
            CP16(da,         (const void*)(g_O   + (size_t)(m0 + row)*CD + (kc)*64 + lc*8)); \
            CP16(da + 16384, (const void*)(g_Wob + (size_t)row*CD        + (kc)*64 + lc*8)); \
        }                                                                     \
    } while(0)

    uint32_t hacc[4][8][2];
    #pragma unroll
    for (int a = 0; a < 4; a++)
        #pragma unroll
        for (int b = 0; b < 8; b++){ hacc[a][b][0] = 0u; hacc[a][b][1] = 0u; }

    uint32_t af[2][4][4], bf[2][4][4];

    #define G2_LDFRAG(buf, ch) do {                                           \
        _Pragma("unroll")                                                     \
        for (int mt = 0; mt < 4; mt++)                                        \
            ldsm4(af[buf][mt][0],af[buf][mt][1],af[buf][mt][2],af[buf][mt][3], sA + rA[mt] + (ch)); \
        _Pragma("unroll")                                                     \
        for (int nb = 0; nb < 4; nb++)                                        \
            ldsm4(bf[buf][nb][0],bf[buf][nb][1],bf[buf][nb][2],bf[buf][nb][3], sB + rB[nb] + (ch)); \
    } while(0)

    #define G2_MMA(buf) do {                                                  \
        _Pragma("unroll")                                                     \
        for (int mt = 0; mt < 4; mt++)                                        \
            _Pragma("unroll")                                                 \
            for (int nb = 0; nb < 4; nb++){                                   \
                mma16816h(hacc[mt][nb*2],   af[buf][mt], bf[buf][nb][0], bf[buf][nb][2]); \
                mma16816h(hacc[mt][nb*2+1], af[buf][mt], bf[buf][nb][1], bf[buf][nb][3]); \
            }                                                                 \
    } while(0)

    G2_LOAD(0, 0); CP_COMMIT();

    #pragma unroll 1
    for (int kc = 0; kc < 16; kc++){
        if (kc + 1 < 16){ G2_LOAD(kc+1, (kc+1)&1); CP_COMMIT(); CP_WAIT(1); }
        else { CP_WAIT(0); }
        __syncthreads();
        const uint32_t sA = sb + (kc&1)*32768;
        const uint32_t sB = sA + 16384;
        G2_LDFRAG(0, (hi ^ lo7) << 4);
        #pragma unroll
        for (int ks = 0; ks < 4; ks++){
            if (ks < 3){
                int chn = (((ks+1)*2 + hi) ^ lo7) << 4;
                G2_LDFRAG((ks+1)&1, chn);
            }
            G2_MMA(ks&1);
        }
        __syncthreads();
    }

    // direct fused epilogue: (z+bo)*invn + Zraw  (unpack half2 accumulators)
    const int rbase = lane >> 2, cpair = (lane & 3)*2;
    #pragma unroll
    for (int mt = 0; mt < 4; mt++){
        int mA = m0 + mw0 + mt*16 + rbase;
        int mB = mA + 8;
        float invA = 1.0f / (0.001f + g_normv[mA]);
        float invB = 1.0f / (0.001f + g_normv[mB]);
        #pragma unroll
        for (int nt = 0; nt < 8; nt++){
            int o = o0 + nt*8 + cpair;
            float b0 = sbo[o], b1 = sbo[o+1];
            float2 vA = __half22float2(*(__half2*)&hacc[mt][nt][0]);
            float2 vB = __half22float2(*(__half2*)&hacc[mt][nt][1]);
            float2 zA = *(const float2*)(Zraw + (size_t)mA*NOUT + o);
            float2 zB = *(const float2*)(Zraw + (size_t)mB*NOUT + o);
            float2 rrA, rrB;
            rrA.x = (vA.x + b0)*invA + zA.x;
            rrA.y = (vA.y + b1)*invA + zA.y;
            rrB.x = (vB.x + b0)*invB + zB.x;
            rrB.y = (vB.y + b1)*invB + zB.y;
            *(float2*)(out + (size_t)mA*NOUT + o) = rrA;
            *(float2*)(out + (size_t)mB*NOUT + o) = rrB;
        }
    }
}

// ---------------------------------------------------------------------------
extern "C" void kernel_launch(void* const* d_in, const int* in_sizes, int n_in,
                              void* d_out, int out_size)
{
    const float* M     = (const float*)d_in[0];
    const float* mask  = (const float*)d_in[1];
    const float* Zraw  = (const float*)d_in[2];
    const float* gamma = (const float*)d_in[3];
    const float* beta  = (const float*)d_in[4];
    const float* Wa    = (const float*)d_in[5];
    const float* ba    = (const float*)d_in[6];
    const float* Wb    = (const float*)d_in[7];
    const float* bb    = (const float*)d_in[8];
    const float* Wo    = (const float*)d_in[9];
    const float* bo    = (const float*)d_in[10];
    float* out = (float*)d_out;

    cudaFuncSetAttribute(prep_kernel,  cudaFuncAttributeMaxDynamicSharedMemorySize, PREP_SMEM);
    cudaFuncSetAttribute(gemm1_kernel, cudaFuncAttributeMaxDynamicSharedMemorySize, G1_SMEM);
    cudaFuncSetAttribute(gemm2_kernel, cudaFuncAttributeMaxDynamicSharedMemorySize, G2_SMEM);

    prep_kernel<<<NRES, 256, PREP_SMEM>>>(M, mask, gamma, beta, Wa, ba, Wb, bb);
    norm_kernel<<<NRES, NRES>>>(mask);
    wconv_kernel<<<512, 256>>>(Wo);
    gemm1_kernel<<<dim3(96, 96), 128, G1_SMEM>>>();
    gemm2_kernel<<<NPAIR/128, 128, G2_SMEM>>>(Zraw, bo, out);
}